// round 16
// baseline (speedup 1.0000x reference)
#include <cuda_runtime.h>
#include <math.h>
#include <float.h>

#define BB 64
#define NN 32768
#define CC 2
#define KK 10
#define QTA 16                 // minseg chunk-blocks per batch
#define CHA (NN / QTA)         // 2048 columns per minseg block
#define WSEG (CHA / 8)         // 256 columns per warp (2 segments)
#define NSEG 256               // segments per row
#define SEGSZ 128              // columns per segment
#define CAPS 1024              // smem candidate pool per (b,row)
#define NMINSEG (BB * QTA)     // 1024
#define FULLM 0xffffffffu
#define MAXC 0x7fffffff

// fast sigmoid for cost scanning — identical instruction sequence in both
// phases (tau bound relies on bit-identical recomputation).
static __device__ __forceinline__ float fsig(float x) {
    return __fdividef(1.0f, 1.0f + __expf(-x));
}
// shared feature computation; explicit fmaf for determinism
static __device__ __forceinline__ float4 features(float a, float bq, float l0, float l1) {
    float s  = fsig(a);
    float e  = fsig(bq);
    float c0 = fsig(l0);
    float c1 = fsig(l1);
    float base = fmaf(s, s, fmaf(e, e, fmaf(c0, c0, fmaf(c1, c1, 1.0f))));
    return make_float4(s, e, fmaf(-2.0f, c0, base), fmaf(-2.0f, c1, base));
}
// accurate versions for the final loss terms
static __device__ __forceinline__ float sigmoidf_(float x) {
    return 1.0f / (1.0f + expf(-x));
}
static __device__ __forceinline__ float softplusf_(float x) {
    return fmaxf(x, 0.0f) + log1pf(expf(-fabsf(x)));
}

__device__ float g_segmin[BB * KK * NSEG];
__device__ float g_cand_val[BB * KK * KK];   // sorted top-10 per (b,row)
__device__ int   g_cand_col[BB * KK * KK];
__device__ int   g_bdone[BB];                // minseg arrivals per batch
__device__ int   g_bdone2[BB];               // filter arrivals per batch
__device__ float g_bpart[BB];
__device__ float g_bm[BB];
__device__ int   g_done;

// ---------------------------------------------------------------------------
// ONE launch. Blocks [0, 1024): minseg for (b, chunk), arrive, exit.
// Blocks [1024, 1664): filter for (b, row) after spinning on the batch
// counter; 10th filter of a batch runs match; global last runs finalize.
// ---------------------------------------------------------------------------
__global__ __launch_bounds__(256) void pipeline_kernel(
        const float* __restrict__ ps,
        const float* __restrict__ pe,
        const float* __restrict__ pcl,
        const float* __restrict__ pcf,
        const float* __restrict__ gt,
        float* __restrict__ out) {
    __shared__ float ssm[NSEG];
    __shared__ int   qseg[NSEG];
    __shared__ int   s_nq, s_cnt;
    __shared__ float s_tau;
    __shared__ float bufv[CAPS];
    __shared__ int   bufc[CAPS];
    __shared__ float sval[KK * KK];
    __shared__ int   scol[KK * KK];
    __shared__ float s_fs[KK], s_fe[KK];
    __shared__ int   s_cli[KK];
    __shared__ int   s_mk[KK], s_mcol[KK];
    __shared__ int   s_nm;
    __shared__ float s_loss[KK];
    __shared__ int   s_isl, s_last;
    __shared__ float sP[BB], sM[BB];

    int tid = threadIdx.x;
    int w = tid >> 5;
    int lane = tid & 31;

    // =====================================================================
    // MINSEG BLOCKS
    // =====================================================================
    if (blockIdx.x < NMINSEG) {
        int b = blockIdx.x >> 4;
        int chunk = blockIdx.x & (QTA - 1);

        float ms[KK], me[KK]; bool cls0[KK];
#pragma unroll
        for (int k = 0; k < KK; k++) {
            const float* g = gt + (size_t)(b * KK + k) * 3;
            float a = g[0], c = g[1], d = g[2];
            bool p = !((a != a) || (c != c) || (d != d));
            if (p) {
                int ci = (int)d;
                ci = ci < 0 ? 0 : (ci > CC - 1 ? CC - 1 : ci);
                ms[k] = -2.0f * a; me[k] = -2.0f * c; cls0[k] = (ci == 0);
            } else {
                ms[k] = 0.0f; me[k] = 0.0f; cls0[k] = true;
            }
        }

        const float4* ps4  = reinterpret_cast<const float4*>(ps + (size_t)b * NN);
        const float4* pe4  = reinterpret_cast<const float4*>(pe + (size_t)b * NN);
        const float4* pcl4 = reinterpret_cast<const float4*>(pcl + (size_t)b * NN * 2);
        int cb4 = (chunk * CHA + w * WSEG) >> 2;

#pragma unroll
        for (int q = 0; q < 2; q++) {           // 2 segments of 128 cols each
            float rmin[KK];
#pragma unroll
            for (int k = 0; k < KK; k++) rmin[k] = FLT_MAX;

            int i4 = cb4 + q * 32 + lane;
            float4 A  = ps4[i4];
            float4 Bq = pe4[i4];
            float4 L0 = pcl4[2 * i4];
            float4 L1 = pcl4[2 * i4 + 1];
            float av[4]  = {A.x, A.y, A.z, A.w};
            float bv2[4] = {Bq.x, Bq.y, Bq.z, Bq.w};
            float l0v[4] = {L0.x, L0.z, L1.x, L1.z};
            float l1v[4] = {L0.y, L0.w, L1.y, L1.w};
#pragma unroll
            for (int j = 0; j < 4; j++) {
                float4 f = features(av[j], bv2[j], l0v[j], l1v[j]);
#pragma unroll
                for (int k = 0; k < KK; k++) {
                    float v = fmaf(f.x, ms[k], fmaf(f.y, me[k], cls0[k] ? f.z : f.w));
                    rmin[k] = fminf(rmin[k], v);
                }
            }

            int seg = chunk * 16 + w * 2 + q;
#pragma unroll
            for (int k = 0; k < KK; k++) {
                float m = rmin[k];
#pragma unroll
                for (int o = 16; o; o >>= 1) m = fminf(m, __shfl_xor_sync(FULLM, m, o));
                if (lane == 0) g_segmin[(b * KK + k) * NSEG + seg] = m;
            }
        }

        __threadfence();
        __syncthreads();
        if (tid == 0) atomicAdd(&g_bdone[b], 1);
        return;                                 // minseg blocks exit
    }

    // =====================================================================
    // FILTER BLOCKS
    // =====================================================================
    int fid = blockIdx.x - NMINSEG;
    int b = fid / KK;
    int row = fid % KK;
    int obase = (b * KK + row) * KK;

    // independent-input preamble (overlaps the spin)
    const float* g = gt + (size_t)(b * KK + row) * 3;
    float fs = g[0], fe = g[1], cl = g[2];
    bool present = !((fs != fs) || (fe != fe) || (cl != cl));
    if (tid == 0) { s_nq = 0; s_cnt = 0; }

    // wait for this batch's 16 minseg arrivals (deps are earlier blocks)
    if (tid == 0) {
        while (*(volatile int*)&g_bdone[b] < QTA) __nanosleep(64);
    }
    __syncthreads();

    // ---------------- FILTER PHASE (R15 verbatim) ----------------
    if (!present) {
        if (tid < KK) { g_cand_val[obase + tid] = 1.0e6f; g_cand_col[obase + tid] = tid; }
    } else {
        int ci = (int)cl;
        ci = ci < 0 ? 0 : (ci > CC - 1 ? CC - 1 : ci);
        bool cls0 = (ci == 0);
        float ms = -2.0f * fs, me = -2.0f * fe;
        float ck = fmaf(fs, fs, fe * fe);

        ssm[tid] = g_segmin[(b * KK + row) * NSEG + tid];   // 256 threads = NSEG
        __syncthreads();

        // tau: 10th smallest of 256 segment minima (warp 0, 8 values/lane)
        if (tid < 32) {
            float sv[8];
#pragma unroll
            for (int j = 0; j < 8; j++) sv[j] = ssm[j * 32 + lane];
            float tau = FLT_MAX;
#pragma unroll
            for (int r = 0; r < KK; r++) {
                float mv = sv[0]; int sl = 0;
#pragma unroll
                for (int j = 1; j < 8; j++) if (sv[j] < mv) { mv = sv[j]; sl = j; }
                int src = lane;
#pragma unroll
                for (int o = 16; o; o >>= 1) {
                    float ov = __shfl_xor_sync(FULLM, mv, o);
                    int   os = __shfl_xor_sync(FULLM, src, o);
                    if (ov < mv || (ov == mv && os < src)) { mv = ov; src = os; }
                }
                if (lane == src) {
#pragma unroll
                    for (int j = 0; j < 8; j++) if (j == sl) sv[j] = FLT_MAX;
                }
                tau = mv;
            }
            if (lane == 0) s_tau = tau;
        }
        __syncthreads();
        float tau = s_tau;

        // qualifying segment list
        if (ssm[tid] <= tau) {
            int p = atomicAdd(&s_nq, 1);
            qseg[p] = tid;
        }
        __syncthreads();
        int nq = s_nq;
        int total = nq * SEGSZ;

        const float*  psb  = ps + (size_t)b * NN;
        const float*  peb  = pe + (size_t)b * NN;
        const float2* pcl2 = reinterpret_cast<const float2*>(pcl + (size_t)b * NN * 2);

        for (int i = tid; i < total; i += 256) {
            int seg = qseg[i >> 7];
            int col = (seg << 7) + (i & (SEGSZ - 1));
            float2 L = pcl2[col];
            float4 f = features(psb[col], peb[col], L.x, L.y);
            float v = fmaf(f.x, ms, fmaf(f.y, me, cls0 ? f.z : f.w));
            if (v <= tau) {
                int p = atomicAdd(&s_cnt, 1);
                if (p < CAPS) { bufv[p] = v; bufc[p] = col; }
            }
        }
        __syncthreads();

        // parallel rank-select: exact sorted top-10 by (val, col) lex order.
        int cnt = s_cnt; if (cnt > CAPS) cnt = CAPS;
        for (int i = tid; i < cnt; i += 256) {
            float vi = bufv[i]; int ci2 = bufc[i];
            int rank = 0;
            for (int j = 0; j < cnt; j++) {
                float vj = bufv[j]; int cj = bufc[j];
                rank += (vj < vi || (vj == vi && cj < ci2)) ? 1 : 0;
            }
            if (rank < KK) {
                g_cand_val[obase + rank] = vi + ck;   // restore row constant
                g_cand_col[obase + rank] = ci2;
            }
        }
    }

    // ---------------- per-batch completion ----------------
    __threadfence();
    __syncthreads();
    if (tid == 0) {
        int t = atomicAdd(&g_bdone2[b], 1);
        s_isl = (t == KK - 1) ? 1 : 0;
        if (s_isl) { g_bdone[b] = 0; g_bdone2[b] = 0; }  // replay-safe reset
    }
    __syncthreads();
    if (!s_isl) return;

    // ---------------- MATCH PHASE (last filter block of batch b) ----------
    for (int i = tid; i < KK * KK; i += 256) {
        sval[i] = g_cand_val[b * KK * KK + i];
        scol[i] = g_cand_col[b * KK * KK + i];
    }
    if (tid < KK) {
        const float* gg = gt + (size_t)(b * KK + tid) * 3;
        float a = gg[0], c = gg[1], d = gg[2];
        bool p = !((a != a) || (c != c) || (d != d));
        s_fs[tid] = (a != a) ? 0.0f : a;
        s_fe[tid] = (c != c) ? 0.0f : c;
        d = (d != d) ? 0.0f : d;
        int ci = (int)d;
        ci = ci < 0 ? 0 : (ci > CC - 1 ? CC - 1 : ci);
        s_cli[tid] = p ? ci : -1;
    }
    __syncthreads();

    // warp-parallel greedy match (warp 0, lane k owns row k)
    if (w == 0) {
        bool active = (lane < KK) && (s_cli[lane] >= 0);
        int ptr = 0;
        int usedc[KK];
        int nused = 0;
        int nm = 0;
        for (int it = 0; it < KK; it++) {
            float myv = FLT_MAX; int mycol = MAXC;
            if (active) {
                while (ptr < KK) {
                    int col = scol[lane * KK + ptr];
                    bool isused = false;
                    for (int u = 0; u < nused; u++) isused |= (usedc[u] == col);
                    if (!isused) { myv = sval[lane * KK + ptr]; mycol = col; break; }
                    ptr++;
                }
            }
            float bvv = myv; int brow = lane; int bcol = mycol;
#pragma unroll
            for (int o = 16; o; o >>= 1) {
                float ov = __shfl_xor_sync(FULLM, bvv, o);
                int   orw = __shfl_xor_sync(FULLM, brow, o);
                int   ocl = __shfl_xor_sync(FULLM, bcol, o);
                if (ov < bvv || (ov == bvv && orw < brow)) { bvv = ov; brow = orw; bcol = ocl; }
            }
            if (bvv == FLT_MAX) break;
            usedc[nused++] = bcol;
            if (lane == brow) active = false;
            if (bvv < 0.5e6f) {
                if (lane == 0) { s_mk[nm] = brow; s_mcol[nm] = bcol; }
                nm++;
            }
        }
        if (lane == 0) s_nm = nm;
    }
    __syncthreads();

    // exact loss terms in parallel
    int nm = s_nm;
    if (tid < KK) {
        float part = 0.0f;
        if (tid < nm) {
            int k = s_mk[tid];
            int col = s_mcol[tid];
            size_t idx = (size_t)b * NN + col;
            float ss = sigmoidf_(ps[idx]);
            float se = sigmoidf_(pe[idx]);
            float gs = s_fs[k], ge = s_fe[k];
            float dls = ss - gs, dle = se - ge;
            part = dls * dls + dle * dle;                            // loc
            float l0 = pcl[idx * 2], l1 = pcl[idx * 2 + 1];
            part += (s_cli[k] == 0) ? (softplusf_(-l0) + softplusf_(l1))
                                    : (softplusf_(l0) + softplusf_(-l1));  // class
            float a1 = fminf(ss, se), b1 = fmaxf(ss, se);
            float a2 = fminf(gs, ge), b2 = fmaxf(gs, ge);
            float inter = fmaxf(0.0f, fminf(b1, b2) - fmaxf(a1, a2));
            float uni = fmaxf(1e-8f, fmaxf(b1, b2) - fminf(a1, a2));
            float iou = inter / uni;
            float dcf = sigmoidf_(pcf[idx]) - iou;
            part += dcf * dcf;                                       // conf
        }
        s_loss[tid] = part;
    }
    __syncthreads();

    if (tid == 0) {
        float tot = 0.0f;
#pragma unroll
        for (int j = 0; j < KK; j++) tot += s_loss[j];
        g_bpart[b] = tot;
        g_bm[b] = (float)nm;
        __threadfence();
        int t = atomicAdd(&g_done, 1);
        s_last = (t == BB - 1) ? 1 : 0;
    }
    __syncthreads();

    // global finalize: last match block reduces
    if (s_last) {
        if (tid < BB) {
            sP[tid] = g_bpart[tid];
            sM[tid] = g_bm[tid];
        }
        __syncthreads();
        if (tid == 0) {
            float P = 0.0f, M = 0.0f;
#pragma unroll
            for (int i = 0; i < BB; i++) { P += sP[i]; M += sM[i]; }
            g_done = 0;   // reset for next graph replay
            out[0] = (M > 0.0f) ? (P / (M + 1e-8f)) : 0.0f;
        }
    }
}

// ---------------------------------------------------------------------------
extern "C" void kernel_launch(void* const* d_in, const int* in_sizes, int n_in,
                              void* d_out, int out_size) {
    const float* ps  = (const float*)d_in[0];   // (B, N)
    const float* pe  = (const float*)d_in[1];   // (B, N)
    const float* pcl = (const float*)d_in[2];   // (B, N, 2)
    const float* pcf = (const float*)d_in[3];   // (B, N)
    const float* gt  = (const float*)d_in[4];   // (B, K, 3)
    float* out = (float*)d_out;

    pipeline_kernel<<<NMINSEG + BB * KK, 256>>>(ps, pe, pcl, pcf, gt, out);
}

// round 17
// speedup vs baseline: 1.2088x; 1.2088x over previous
#include <cuda_runtime.h>
#include <math.h>
#include <float.h>

#define BB 64
#define NN 32768
#define CC 2
#define KK 10
#define QTA 16                 // chunks per row, kernel A
#define CHA (NN / QTA)         // 2048 columns per block
#define WSEG (CHA / 8)         // 256 columns per warp (2 segments)
#define NSEG 256               // segments per row
#define SEGSZ 128              // columns per segment
#define CAPS 1024              // smem candidate pool per (b,row)
#define FULLM 0xffffffffu
#define MAXC 0x7fffffff

// fast sigmoid for cost scanning — identical instruction sequence in both
// kernels (tau bound relies on bit-identical recomputation).
static __device__ __forceinline__ float fsig(float x) {
    return __fdividef(1.0f, 1.0f + __expf(-x));
}
// shared feature computation; explicit fmaf for determinism
static __device__ __forceinline__ float4 features(float a, float bq, float l0, float l1) {
    float s  = fsig(a);
    float e  = fsig(bq);
    float c0 = fsig(l0);
    float c1 = fsig(l1);
    float base = fmaf(s, s, fmaf(e, e, fmaf(c0, c0, fmaf(c1, c1, 1.0f))));
    return make_float4(s, e, fmaf(-2.0f, c0, base), fmaf(-2.0f, c1, base));
}
// accurate versions for the final loss terms
static __device__ __forceinline__ float sigmoidf_(float x) {
    return 1.0f / (1.0f + expf(-x));
}
static __device__ __forceinline__ float softplusf_(float x) {
    return fmaxf(x, 0.0f) + log1pf(expf(-fabsf(x)));
}

// order-preserving float<->uint encoding (f1 < f2  <=>  fenc(f1) < fenc(f2))
static __device__ __forceinline__ unsigned fenc(float f) {
    unsigned u = __float_as_uint(f);
    return u ^ ((unsigned)(((int)u) >> 31) | 0x80000000u);
}
static __device__ __forceinline__ float fdec(unsigned u) {
    u ^= ((unsigned)(((int)(u ^ 0x80000000u)) >> 31) | 0x80000000u);
    return __uint_as_float(u);
}

__device__ unsigned g_segmin[BB * KK * NSEG];   // encoded segment minima
__device__ float g_cand_val[BB * KK * KK];      // sorted top-10 per (b,row)
__device__ int   g_cand_col[BB * KK * KK];
__device__ int   g_bdone[BB];
__device__ float g_bpart[BB];
__device__ float g_bm[BB];
__device__ int   g_done;

// ---------------------------------------------------------------------------
// Kernel A: per-(row, 128-col segment) minimum of shifted cost (encoded).
// ---------------------------------------------------------------------------
__global__ __launch_bounds__(256) void minseg_kernel(
        const float* __restrict__ ps,
        const float* __restrict__ pe,
        const float* __restrict__ pcl,
        const float* __restrict__ gt) {
    int b = blockIdx.x >> 4;
    int chunk = blockIdx.x & (QTA - 1);
    int w = threadIdx.x >> 5;
    int lane = threadIdx.x & 31;

    float ms[KK], me[KK]; bool cls0[KK];
#pragma unroll
    for (int k = 0; k < KK; k++) {
        const float* g = gt + (size_t)(b * KK + k) * 3;
        float a = g[0], c = g[1], d = g[2];
        bool p = !((a != a) || (c != c) || (d != d));
        if (p) {
            int ci = (int)d;
            ci = ci < 0 ? 0 : (ci > CC - 1 ? CC - 1 : ci);
            ms[k] = -2.0f * a; me[k] = -2.0f * c; cls0[k] = (ci == 0);
        } else {
            ms[k] = 0.0f; me[k] = 0.0f; cls0[k] = true;
        }
    }

    const float4* ps4  = reinterpret_cast<const float4*>(ps + (size_t)b * NN);
    const float4* pe4  = reinterpret_cast<const float4*>(pe + (size_t)b * NN);
    const float4* pcl4 = reinterpret_cast<const float4*>(pcl + (size_t)b * NN * 2);
    int cb4 = (chunk * CHA + w * WSEG) >> 2;

#pragma unroll
    for (int q = 0; q < 2; q++) {               // 2 segments of 128 cols each
        float rmin[KK];
#pragma unroll
        for (int k = 0; k < KK; k++) rmin[k] = FLT_MAX;

        int i4 = cb4 + q * 32 + lane;
        float4 A  = ps4[i4];
        float4 Bq = pe4[i4];
        float4 L0 = pcl4[2 * i4];
        float4 L1 = pcl4[2 * i4 + 1];
        float av[4]  = {A.x, A.y, A.z, A.w};
        float bv[4]  = {Bq.x, Bq.y, Bq.z, Bq.w};
        float l0v[4] = {L0.x, L0.z, L1.x, L1.z};
        float l1v[4] = {L0.y, L0.w, L1.y, L1.w};
#pragma unroll
        for (int j = 0; j < 4; j++) {
            float4 f = features(av[j], bv[j], l0v[j], l1v[j]);
#pragma unroll
            for (int k = 0; k < KK; k++) {
                float v = fmaf(f.x, ms[k], fmaf(f.y, me[k], cls0[k] ? f.z : f.w));
                rmin[k] = fminf(rmin[k], v);
            }
        }

        int seg = chunk * 16 + w * 2 + q;
#pragma unroll
        for (int k = 0; k < KK; k++) {
            unsigned em = __reduce_min_sync(FULLM, fenc(rmin[k]));
            if (lane == 0) g_segmin[(b * KK + k) * NSEG + seg] = em;
        }
    }
}

// ---------------------------------------------------------------------------
// Kernel B: one block per (b, row): tau (REDUX rounds) + pruned rescan
// (2x unrolled) -> sorted top-10 via rank-select; per-batch last block:
// greedy match + losses; global last: final reduce. Launched with PDL.
// ---------------------------------------------------------------------------
__global__ __launch_bounds__(256) void filter_match_kernel(
        const float* __restrict__ ps,
        const float* __restrict__ pe,
        const float* __restrict__ pcl,
        const float* __restrict__ pcf,
        const float* __restrict__ gt,
        float* __restrict__ out) {
    __shared__ unsigned ssm[NSEG];
    __shared__ int   qseg[NSEG];
    __shared__ int   s_nq, s_cnt;
    __shared__ unsigned s_tauE;
    __shared__ float bufv[CAPS];
    __shared__ int   bufc[CAPS];
    // match phase
    __shared__ float sval[KK * KK];
    __shared__ int   scol[KK * KK];
    __shared__ float s_fs[KK], s_fe[KK];
    __shared__ int   s_cli[KK];
    __shared__ int   s_mk[KK], s_mcol[KK];
    __shared__ int   s_nm;
    __shared__ float s_loss[KK];
    __shared__ int   s_isl, s_last;
    __shared__ float sP[BB], sM[BB];

    int b = blockIdx.x / KK;
    int row = blockIdx.x % KK;
    int tid = threadIdx.x;
    int lane = tid & 31;
    int w = tid >> 5;
    int obase = (b * KK + row) * KK;

    // independent-input preamble (overlaps primary kernel under PDL)
    const float* g = gt + (size_t)(b * KK + row) * 3;
    float fs = g[0], fe = g[1], cl = g[2];
    bool present = !((fs != fs) || (fe != fe) || (cl != cl));
    if (tid == 0) { s_nq = 0; s_cnt = 0; }

    // wait for minseg's g_segmin writes to be visible
    cudaGridDependencySynchronize();

    // ================= FILTER PHASE =================
    if (!present) {
        if (tid < KK) { g_cand_val[obase + tid] = 1.0e6f; g_cand_col[obase + tid] = tid; }
    } else {
        int ci = (int)cl;
        ci = ci < 0 ? 0 : (ci > CC - 1 ? CC - 1 : ci);
        bool cls0 = (ci == 0);
        float ms = -2.0f * fs, me = -2.0f * fe;
        float ck = fmaf(fs, fs, fe * fe);

        ssm[tid] = g_segmin[(b * KK + row) * NSEG + tid];   // 256 threads = NSEG
        __syncthreads();

        // tau: 10th smallest of 256 encoded segmins (warp 0, REDUX rounds)
        if (tid < 32) {
            unsigned sv[8];
#pragma unroll
            for (int j = 0; j < 8; j++) sv[j] = ssm[j * 32 + lane];
            unsigned tauE = 0xFFFFFFFFu;
#pragma unroll
            for (int r = 0; r < KK; r++) {
                unsigned m01 = min(sv[0], sv[1]);
                unsigned m23 = min(sv[2], sv[3]);
                unsigned m45 = min(sv[4], sv[5]);
                unsigned m67 = min(sv[6], sv[7]);
                unsigned mv = min(min(m01, m23), min(m45, m67));
                unsigned rm = __reduce_min_sync(FULLM, mv);
                unsigned bal = __ballot_sync(FULLM, mv == rm);
                int src = __ffs((int)bal) - 1;
                if (lane == src) {
                    bool done = false;
#pragma unroll
                    for (int j = 0; j < 8; j++) {
                        if (!done && sv[j] == rm) { sv[j] = 0xFFFFFFFFu; done = true; }
                    }
                }
                tauE = rm;
            }
            if (lane == 0) s_tauE = tauE;
        }
        __syncthreads();
        unsigned tauE = s_tauE;
        float tau = fdec(tauE);

        // qualifying segment list (encoded compare, order-preserving)
        if (ssm[tid] <= tauE) {
            int p = atomicAdd(&s_nq, 1);
            qseg[p] = tid;
        }
        __syncthreads();
        int nq = s_nq;
        int total = nq * SEGSZ;

        const float*  psb  = ps + (size_t)b * NN;
        const float*  peb  = pe + (size_t)b * NN;
        const float2* pcl2 = reinterpret_cast<const float2*>(pcl + (size_t)b * NN * 2);

        // scan qualifying segments, 2 items per iteration for MLP
        int i = tid;
        for (; i + 256 < total; i += 512) {
            int iB = i + 256;
            int colA = (qseg[i >> 7] << 7) + (i & (SEGSZ - 1));
            int colB = (qseg[iB >> 7] << 7) + (iB & (SEGSZ - 1));
            float aA = psb[colA], aB = psb[colB];
            float eA = peb[colA], eB = peb[colB];
            float2 LA = pcl2[colA], LB = pcl2[colB];
            float4 fA = features(aA, eA, LA.x, LA.y);
            float4 fB = features(aB, eB, LB.x, LB.y);
            float vA = fmaf(fA.x, ms, fmaf(fA.y, me, cls0 ? fA.z : fA.w));
            float vB = fmaf(fB.x, ms, fmaf(fB.y, me, cls0 ? fB.z : fB.w));
            if (vA <= tau) {
                int p = atomicAdd(&s_cnt, 1);
                if (p < CAPS) { bufv[p] = vA; bufc[p] = colA; }
            }
            if (vB <= tau) {
                int p = atomicAdd(&s_cnt, 1);
                if (p < CAPS) { bufv[p] = vB; bufc[p] = colB; }
            }
        }
        if (i < total) {
            int col = (qseg[i >> 7] << 7) + (i & (SEGSZ - 1));
            float2 L = pcl2[col];
            float4 f = features(psb[col], peb[col], L.x, L.y);
            float v = fmaf(f.x, ms, fmaf(f.y, me, cls0 ? f.z : f.w));
            if (v <= tau) {
                int p = atomicAdd(&s_cnt, 1);
                if (p < CAPS) { bufv[p] = v; bufc[p] = col; }
            }
        }
        __syncthreads();

        // parallel rank-select: exact sorted top-10 by (val, col) lex order.
        // cnt >= 10 guaranteed (the 10 smallest segmins are real items <= tau).
        int cnt = s_cnt; if (cnt > CAPS) cnt = CAPS;
        for (int ii = tid; ii < cnt; ii += 256) {
            float vi = bufv[ii]; int ci2 = bufc[ii];
            int rank = 0;
            for (int j = 0; j < cnt; j++) {
                float vj = bufv[j]; int cj = bufc[j];
                rank += (vj < vi || (vj == vi && cj < ci2)) ? 1 : 0;
            }
            if (rank < KK) {
                g_cand_val[obase + rank] = vi + ck;   // restore row constant
                g_cand_col[obase + rank] = ci2;
            }
        }
    }

    // ================= per-batch completion =================
    __threadfence();
    __syncthreads();
    if (tid == 0) {
        int t = atomicAdd(&g_bdone[b], 1);
        s_isl = (t == KK - 1) ? 1 : 0;
        if (s_isl) g_bdone[b] = 0;   // reset for next graph replay
    }
    __syncthreads();
    if (!s_isl) return;

    // ================= MATCH PHASE (last block of batch b) =================
    for (int i = tid; i < KK * KK; i += 256) {
        sval[i] = g_cand_val[b * KK * KK + i];
        scol[i] = g_cand_col[b * KK * KK + i];
    }
    if (tid < KK) {
        const float* gg = gt + (size_t)(b * KK + tid) * 3;
        float a = gg[0], c = gg[1], d = gg[2];
        bool p = !((a != a) || (c != c) || (d != d));
        s_fs[tid] = (a != a) ? 0.0f : a;
        s_fe[tid] = (c != c) ? 0.0f : c;
        d = (d != d) ? 0.0f : d;
        int ci = (int)d;
        ci = ci < 0 ? 0 : (ci > CC - 1 ? CC - 1 : ci);
        s_cli[tid] = p ? ci : -1;
    }
    __syncthreads();

    // warp-parallel greedy match (warp 0, lane k owns row k)
    if (w == 0) {
        bool active = (lane < KK) && (s_cli[lane] >= 0);
        int ptr = 0;
        int usedc[KK];
        int nused = 0;
        int nm = 0;
        for (int it = 0; it < KK; it++) {
            float myv = FLT_MAX; int mycol = MAXC;
            if (active) {
                while (ptr < KK) {
                    int col = scol[lane * KK + ptr];
                    bool isused = false;
                    for (int u = 0; u < nused; u++) isused |= (usedc[u] == col);
                    if (!isused) { myv = sval[lane * KK + ptr]; mycol = col; break; }
                    ptr++;
                }
            }
            float bvv = myv; int brow = lane; int bcol = mycol;
#pragma unroll
            for (int o = 16; o; o >>= 1) {
                float ov = __shfl_xor_sync(FULLM, bvv, o);
                int   orw = __shfl_xor_sync(FULLM, brow, o);
                int   ocl = __shfl_xor_sync(FULLM, bcol, o);
                if (ov < bvv || (ov == bvv && orw < brow)) { bvv = ov; brow = orw; bcol = ocl; }
            }
            if (bvv == FLT_MAX) break;
            usedc[nused++] = bcol;
            if (lane == brow) active = false;
            if (bvv < 0.5e6f) {
                if (lane == 0) { s_mk[nm] = brow; s_mcol[nm] = bcol; }
                nm++;
            }
        }
        if (lane == 0) s_nm = nm;
    }
    __syncthreads();

    // exact loss terms in parallel
    int nm = s_nm;
    if (tid < KK) {
        float part = 0.0f;
        if (tid < nm) {
            int k = s_mk[tid];
            int col = s_mcol[tid];
            size_t idx = (size_t)b * NN + col;
            float ss = sigmoidf_(ps[idx]);
            float se = sigmoidf_(pe[idx]);
            float gs = s_fs[k], ge = s_fe[k];
            float dls = ss - gs, dle = se - ge;
            part = dls * dls + dle * dle;                            // loc
            float l0 = pcl[idx * 2], l1 = pcl[idx * 2 + 1];
            part += (s_cli[k] == 0) ? (softplusf_(-l0) + softplusf_(l1))
                                    : (softplusf_(l0) + softplusf_(-l1));  // class
            float a1 = fminf(ss, se), b1 = fmaxf(ss, se);
            float a2 = fminf(gs, ge), b2 = fmaxf(gs, ge);
            float inter = fmaxf(0.0f, fminf(b1, b2) - fmaxf(a1, a2));
            float uni = fmaxf(1e-8f, fmaxf(b1, b2) - fminf(a1, a2));
            float iou = inter / uni;
            float dcf = sigmoidf_(pcf[idx]) - iou;
            part += dcf * dcf;                                       // conf
        }
        s_loss[tid] = part;
    }
    __syncthreads();

    if (tid == 0) {
        float tot = 0.0f;
#pragma unroll
        for (int j = 0; j < KK; j++) tot += s_loss[j];
        g_bpart[b] = tot;
        g_bm[b] = (float)nm;
        __threadfence();
        int t = atomicAdd(&g_done, 1);
        s_last = (t == BB - 1) ? 1 : 0;
    }
    __syncthreads();

    // global finalize: last batch reduces
    if (s_last) {
        if (tid < BB) {
            sP[tid] = g_bpart[tid];
            sM[tid] = g_bm[tid];
        }
        __syncthreads();
        if (tid == 0) {
            float P = 0.0f, M = 0.0f;
#pragma unroll
            for (int i = 0; i < BB; i++) { P += sP[i]; M += sM[i]; }
            g_done = 0;   // reset for next graph replay
            out[0] = (M > 0.0f) ? (P / (M + 1e-8f)) : 0.0f;
        }
    }
}

// ---------------------------------------------------------------------------
extern "C" void kernel_launch(void* const* d_in, const int* in_sizes, int n_in,
                              void* d_out, int out_size) {
    const float* ps  = (const float*)d_in[0];   // (B, N)
    const float* pe  = (const float*)d_in[1];   // (B, N)
    const float* pcl = (const float*)d_in[2];   // (B, N, 2)
    const float* pcf = (const float*)d_in[3];   // (B, N)
    const float* gt  = (const float*)d_in[4];   // (B, K, 3)
    float* out = (float*)d_out;

    minseg_kernel<<<BB * QTA, 256>>>(ps, pe, pcl, gt);

    // PDL launch: overlap secondary launch latency with primary execution.
    cudaLaunchConfig_t cfg = {};
    cfg.gridDim  = dim3(BB * KK, 1, 1);
    cfg.blockDim = dim3(256, 1, 1);
    cfg.dynamicSmemBytes = 0;
    cudaLaunchAttribute attrs[1];
    attrs[0].id = cudaLaunchAttributeProgrammaticStreamSerialization;
    attrs[0].val.programmaticStreamSerializationAllowed = 1;
    cfg.attrs = attrs;
    cfg.numAttrs = 1;
    cudaLaunchKernelEx(&cfg, filter_match_kernel, ps, pe, pcl, pcf, gt, out);
}